// round 1
// baseline (speedup 1.0000x reference)
#include <cuda_runtime.h>
#include <cstdint>

// Problem-size upper bounds (from reference: N=100000, E=3200000)
#define MAXN 100000
#define MAXE 3200000

// ---------------- scratch (device globals; no allocation allowed) ----------
__device__ float g_deg [MAXN];
__device__ float g_dinv[MAXN];
__device__ float g_t1  [MAXN * 64];   // x@W1 (pre-aggregation)
__device__ float g_s   [MAXN * 64];   // node state (h1, then GGC state)
__device__ float g_m   [MAXN * 64];   // per-layer message
__device__ float g_agg [MAXN * 64];   // scatter accumulator
__device__ float g_gi  [MAXN * 192];
__device__ float g_gh  [MAXN * 192];
__device__ float g_t2  [MAXN * 16];   // s@W2 (pre-aggregation)

// ---------------- helpers ---------------------------------------------------
__device__ __forceinline__ void red_add_v4(float* addr, float4 v) {
    asm volatile("red.global.add.v4.f32 [%0], {%1,%2,%3,%4};"
                 :: "l"(addr), "f"(v.x), "f"(v.y), "f"(v.z), "f"(v.w)
                 : "memory");
}

__device__ __forceinline__ float sigmoidf_(float x) {
    return 1.0f / (1.0f + expf(-x));
}

// ---------------- degree / norm ---------------------------------------------
__global__ void init_deg_kernel(float* deg, int n) {
    int i = blockIdx.x * blockDim.x + threadIdx.x;
    if (i < n) deg[i] = 1.0f;              // self-loop weight
}

__global__ void deg_scatter_kernel(float* deg, const int* __restrict__ col,
                                   const float* __restrict__ w, int e) {
    int i = blockIdx.x * blockDim.x + threadIdx.x;
    if (i < e) atomicAdd(deg + col[i], w[i]);
}

__global__ void dinv_kernel(const float* __restrict__ deg, float* __restrict__ dinv, int n) {
    int i = blockIdx.x * blockDim.x + threadIdx.x;
    if (i < n) {
        float d = deg[i];
        dinv[i] = (d > 0.0f) ? (1.0f / sqrtf(d)) : 0.0f;
    }
}

// ---------------- generic register-tiled fp32 GEMM --------------------------
// C[M,Nb] = A[M,K] @ B   ; B is [K,Nb] row-major, or (TRANSB) [Nb,K] row-major.
template<int BM, int BN, int BK, int TM, int TN, bool TRANSB>
__global__ __launch_bounds__((BM/TM)*(BN/TN))
void gemm_kernel(const float* __restrict__ A, const float* __restrict__ B,
                 float* __restrict__ C, int M, int K, int Nb) {
    constexpr int NT  = (BM / TM) * (BN / TN);
    constexpr int BMP = BM + 4;
    constexpr int BNP = BN + 4;
    __shared__ float As[BK][BMP];
    __shared__ float Bs[BK][BNP];

    const int tid = threadIdx.x;
    const int tr  = tid / (BN / TN);
    const int tc  = tid % (BN / TN);
    const int cm  = blockIdx.x * BM;
    const int cn  = blockIdx.y * BN;

    float acc[TM][TN];
#pragma unroll
    for (int i = 0; i < TM; i++)
#pragma unroll
        for (int j = 0; j < TN; j++) acc[i][j] = 0.0f;

    for (int k0 = 0; k0 < K; k0 += BK) {
        // A tile (transposed into SMEM)
#pragma unroll
        for (int s = tid; s < BM * BK / 4; s += NT) {
            int arow = s / (BK / 4);
            int ac4  = s % (BK / 4);
            float4 v = make_float4(0.f, 0.f, 0.f, 0.f);
            int gr = cm + arow;
            if (gr < M)
                v = *reinterpret_cast<const float4*>(A + (size_t)gr * K + k0 + ac4 * 4);
            As[ac4 * 4 + 0][arow] = v.x;
            As[ac4 * 4 + 1][arow] = v.y;
            As[ac4 * 4 + 2][arow] = v.z;
            As[ac4 * 4 + 3][arow] = v.w;
        }
        // B tile
        if (!TRANSB) {
#pragma unroll
            for (int s = tid; s < BK * BN / 4; s += NT) {
                int brow = s / (BN / 4);
                int bc4  = s % (BN / 4);
                float4 v = *reinterpret_cast<const float4*>(
                    B + (size_t)(k0 + brow) * Nb + cn + bc4 * 4);
                Bs[brow][bc4 * 4 + 0] = v.x;
                Bs[brow][bc4 * 4 + 1] = v.y;
                Bs[brow][bc4 * 4 + 2] = v.z;
                Bs[brow][bc4 * 4 + 3] = v.w;
            }
        } else {
#pragma unroll
            for (int s = tid; s < BK * BN; s += NT) {
                int kk = s % BK;
                int nn = s / BK;
                Bs[kk][nn] = B[(size_t)(cn + nn) * K + k0 + kk];
            }
        }
        __syncthreads();

#pragma unroll
        for (int kk = 0; kk < BK; kk++) {
            float a[TM], b[TN];
#pragma unroll
            for (int i = 0; i < TM; i++) a[i] = As[kk][tr * TM + i];
#pragma unroll
            for (int j = 0; j < TN; j++) b[j] = Bs[kk][tc * TN + j];
#pragma unroll
            for (int i = 0; i < TM; i++)
#pragma unroll
                for (int j = 0; j < TN; j++) acc[i][j] = fmaf(a[i], b[j], acc[i][j]);
        }
        __syncthreads();
    }

#pragma unroll
    for (int i = 0; i < TM; i++) {
        int gr = cm + tr * TM + i;
        if (gr < M) {
            float4 v = make_float4(acc[i][0], acc[i][1], acc[i][2], acc[i][3]);
            *reinterpret_cast<float4*>(C + (size_t)gr * Nb + cn + tc * TN) = v;
        }
    }
}

// ---------------- edge scatter (gather src row, red.add into dst row) -------
template<int F, bool USE_NORM>
__global__ void scatter_kernel(const float* __restrict__ src, float* __restrict__ dst,
                               const int* __restrict__ row, const int* __restrict__ col,
                               const float* __restrict__ w, const float* __restrict__ dinv,
                               int e) {
    constexpr int LPE = F / 4;                 // lanes per edge
    long long gtid = (long long)blockIdx.x * blockDim.x + threadIdx.x;
    int ei = (int)(gtid / LPE);
    int l  = (int)(gtid % LPE);
    if (ei >= e) return;
    int r = __ldg(row + ei);
    int c = __ldg(col + ei);
    float ww = __ldg(w + ei);
    float nrm = USE_NORM ? __ldg(dinv + r) * ww * __ldg(dinv + c) : ww;
    float4 v = *reinterpret_cast<const float4*>(src + (size_t)r * F + l * 4);
    float4 o = make_float4(v.x * nrm, v.y * nrm, v.z * nrm, v.w * nrm);
    red_add_v4(dst + (size_t)c * F + l * 4, o);
}

// ---------------- small elementwise kernels ----------------------------------
// dst[i,f] = t[i,f] * dinv[i]^2   (self-loop term of gcn_norm)
__global__ void selfloop_init64_kernel(const float* __restrict__ t,
                                       const float* __restrict__ dinv,
                                       float* __restrict__ dst, int n) {
    int idx = blockIdx.x * blockDim.x + threadIdx.x;
    if (idx >= n * 64) return;
    int i = idx >> 6;
    float di = dinv[i];
    dst[idx] = t[idx] * di * di;
}

__global__ void bias_relu_kernel(float* __restrict__ h, const float* __restrict__ b, int n) {
    int idx = blockIdx.x * blockDim.x + threadIdx.x;
    if (idx >= n * 64) return;
    float v = h[idx] + b[idx & 63];
    h[idx] = fmaxf(v, 0.0f);
}

__global__ void zero64_kernel(float* __restrict__ p, int n) {
    int idx = blockIdx.x * blockDim.x + threadIdx.x;
    if (idx < n * 16) reinterpret_cast<float4*>(p)[idx] = make_float4(0.f, 0.f, 0.f, 0.f);
}

__global__ void gru_kernel(const float* __restrict__ gi, const float* __restrict__ gh,
                           const float* __restrict__ bih, const float* __restrict__ bhh,
                           float* __restrict__ s, int n) {
    int idx = blockIdx.x * blockDim.x + threadIdx.x;
    if (idx >= n * 64) return;
    int i = idx >> 6;
    int f = idx & 63;
    size_t base = (size_t)i * 192 + f;
    float ir = gi[base]       + bih[f];
    float iz = gi[base + 64]  + bih[64 + f];
    float in_= gi[base + 128] + bih[128 + f];
    float hr = gh[base]       + bhh[f];
    float hz = gh[base + 64]  + bhh[64 + f];
    float hn = gh[base + 128] + bhh[128 + f];
    float r  = sigmoidf_(ir + hr);
    float z  = sigmoidf_(iz + hz);
    float ng = tanhf(in_ + r * hn);
    s[idx] = (1.0f - z) * ng + z * s[idx];
}

// fused: t2 = s @ W2 [N,16]; out_init = t2 * dinv^2 (self-loop)
__global__ void w2_fused_kernel(const float* __restrict__ s, const float* __restrict__ W2,
                                const float* __restrict__ dinv,
                                float* __restrict__ t2, float* __restrict__ out, int n) {
    __shared__ float Wsm[64 * 16];
    for (int i = threadIdx.x; i < 64 * 16; i += blockDim.x) Wsm[i] = W2[i];
    __syncthreads();
    int node = blockIdx.x * 16 + threadIdx.x / 16;
    int c = threadIdx.x & 15;
    if (node >= n) return;
    const float4* srow = reinterpret_cast<const float4*>(s + (size_t)node * 64);
    float acc = 0.0f;
#pragma unroll
    for (int k4 = 0; k4 < 16; k4++) {
        float4 sv = __ldg(srow + k4);
        acc = fmaf(sv.x, Wsm[(k4 * 4 + 0) * 16 + c], acc);
        acc = fmaf(sv.y, Wsm[(k4 * 4 + 1) * 16 + c], acc);
        acc = fmaf(sv.z, Wsm[(k4 * 4 + 2) * 16 + c], acc);
        acc = fmaf(sv.w, Wsm[(k4 * 4 + 3) * 16 + c], acc);
    }
    t2[(size_t)node * 16 + c] = acc;
    float di = dinv[node];
    out[(size_t)node * 16 + c] = acc * di * di;
}

__global__ void logsoftmax_kernel(float* __restrict__ out, const float* __restrict__ b2, int n) {
    int gtid = blockIdx.x * blockDim.x + threadIdx.x;
    int i = gtid / 16;
    int c = gtid & 15;
    if (i >= n) return;
    float v = out[(size_t)i * 16 + c] + b2[c];
    float mx = v;
#pragma unroll
    for (int o = 8; o > 0; o >>= 1)
        mx = fmaxf(mx, __shfl_xor_sync(0xffffffffu, mx, o, 16));
    float ex = expf(v - mx);
    float sm = ex;
#pragma unroll
    for (int o = 8; o > 0; o >>= 1)
        sm += __shfl_xor_sync(0xffffffffu, sm, o, 16);
    out[(size_t)i * 16 + c] = v - mx - logf(sm);
}

// ---------------- launch -----------------------------------------------------
extern "C" void kernel_launch(void* const* d_in, const int* in_sizes, int n_in,
                              void* d_out, int out_size) {
    const float* x   = (const float*)d_in[0];
    const int*   ei  = (const int*)  d_in[1];
    const float* ew  = (const float*)d_in[2];
    const float* W1  = (const float*)d_in[3];
    const float* b1  = (const float*)d_in[4];
    const float* Wg  = (const float*)d_in[5];
    const float* Wih = (const float*)d_in[6];
    const float* Whh = (const float*)d_in[7];
    const float* bih = (const float*)d_in[8];
    const float* bhh = (const float*)d_in[9];
    const float* W2  = (const float*)d_in[10];
    const float* b2  = (const float*)d_in[11];
    float* out = (float*)d_out;

    const int n = in_sizes[0] / 512;
    const int e = in_sizes[2];
    const int* row = ei;
    const int* col = ei + e;

    float *deg, *dinv, *t1, *s, *m, *agg, *gi, *gh, *t2;
    cudaGetSymbolAddress((void**)&deg,  g_deg);
    cudaGetSymbolAddress((void**)&dinv, g_dinv);
    cudaGetSymbolAddress((void**)&t1,   g_t1);
    cudaGetSymbolAddress((void**)&s,    g_s);
    cudaGetSymbolAddress((void**)&m,    g_m);
    cudaGetSymbolAddress((void**)&agg,  g_agg);
    cudaGetSymbolAddress((void**)&gi,   g_gi);
    cudaGetSymbolAddress((void**)&gh,   g_gh);
    cudaGetSymbolAddress((void**)&t2,   g_t2);

    const int TB = 256;
    const int mblocks = (n + 127) / 128;

    // ---- shared gcn_norm (both GCN convs) ----
    init_deg_kernel<<<(n + TB - 1) / TB, TB>>>(deg, n);
    deg_scatter_kernel<<<(e + TB - 1) / TB, TB>>>(deg, col, ew, e);
    dinv_kernel<<<(n + TB - 1) / TB, TB>>>(deg, dinv, n);

    // ---- GCN conv 1: t1 = x@W1 ; h1 = relu(norm-agg(t1) + b1) ----
    gemm_kernel<128, 64, 16, 8, 4, false><<<dim3(mblocks, 1), 256>>>(x, W1, t1, n, 512, 64);
    selfloop_init64_kernel<<<(n * 64 + TB - 1) / TB, TB>>>(t1, dinv, s, n);
    {
        long long th = (long long)e * 16;
        scatter_kernel<64, true><<<(unsigned)((th + TB - 1) / TB), TB>>>(t1, s, row, col, ew, dinv, e);
    }
    bias_relu_kernel<<<(n * 64 + TB - 1) / TB, TB>>>(s, b1, n);

    // ---- GatedGraphConv: 2 layers of message passing + GRUCell ----
    for (int layer = 0; layer < 2; layer++) {
        gemm_kernel<128, 64, 16, 8, 4, false><<<dim3(mblocks, 1), 256>>>(
            s, Wg + (size_t)layer * 64 * 64, m, n, 64, 64);
        zero64_kernel<<<(n * 16 + TB - 1) / TB, TB>>>(agg, n);
        {
            long long th = (long long)e * 16;
            scatter_kernel<64, false><<<(unsigned)((th + TB - 1) / TB), TB>>>(m, agg, row, col, ew, dinv, e);
        }
        gemm_kernel<128, 64, 16, 8, 4, true><<<dim3(mblocks, 3), 256>>>(agg, Wih, gi, n, 64, 192);
        gemm_kernel<128, 64, 16, 8, 4, true><<<dim3(mblocks, 3), 256>>>(s,   Whh, gh, n, 64, 192);
        gru_kernel<<<(n * 64 + TB - 1) / TB, TB>>>(gi, gh, bih, bhh, s, n);
    }

    // ---- GCN conv 2 (fused s@W2 + self-loop init) + log_softmax ----
    w2_fused_kernel<<<(n + 15) / 16, 256>>>(s, W2, dinv, t2, out, n);
    {
        long long th = (long long)e * 4;
        scatter_kernel<16, true><<<(unsigned)((th + TB - 1) / TB), TB>>>(t2, out, row, col, ew, dinv, e);
    }
    logsoftmax_kernel<<<(n * 16 + TB - 1) / TB, TB>>>(out, b2, n);
}

// round 2
// speedup vs baseline: 1.2429x; 1.2429x over previous
#include <cuda_runtime.h>
#include <cstdint>

#define MAXN 100000
#define MAXE 3200000

// ---------------- scratch (device globals) ----------------------------------
__device__ float g_deg [MAXN];
__device__ float g_dinv[MAXN];
__device__ float g_t1  [MAXN * 64];   // x@W1
__device__ float g_s   [MAXN * 64];   // node state
__device__ float g_u   [MAXN * 64];   // gathered state (GGC)
__device__ float g_gi  [MAXN * 192];
__device__ float g_gh  [MAXN * 192];
__device__ float g_t2  [MAXN * 16];   // s@W2
// CSR
__device__ int   g_off [MAXN + 1];
__device__ int   g_cur [MAXN];        // counts, then fill cursors
__device__ int   g_srcs[MAXE];
__device__ float g_wpl [MAXE];        // plain w   (GGC)
__device__ float g_wnd [MAXE];        // w * dinv[src] (GCN)
__device__ float g_wc  [2 * 64 * 192]; // combined Wg@Wih^T per layer

__device__ __forceinline__ float sigmoidf_(float x) { return 1.0f / (1.0f + expf(-x)); }

// ---------------- CSR build --------------------------------------------------
__global__ void init_kernel(float* deg, int* cnt, int n) {
    int i = blockIdx.x * blockDim.x + threadIdx.x;
    if (i < n) { deg[i] = 1.0f; cnt[i] = 0; }
}

__global__ void count_kernel(const int* __restrict__ col, const float* __restrict__ w,
                             int* cnt, float* deg, int e) {
    int i = blockIdx.x * blockDim.x + threadIdx.x;
    if (i < e) {
        int c = col[i];
        atomicAdd(cnt + c, 1);
        atomicAdd(deg + c, w[i]);
    }
}

__global__ void scan_kernel(const int* __restrict__ cnt, int* __restrict__ off,
                            int* __restrict__ cur, int n) {
    __shared__ int part[1024];
    int t = threadIdx.x;
    int chunk = (n + 1023) >> 10;
    int lo = t * chunk;
    int hi = min(lo + chunk, n);
    int s = 0;
    for (int i = lo; i < hi; i++) s += cnt[i];
    part[t] = s;
    __syncthreads();
    for (int d = 1; d < 1024; d <<= 1) {
        int add = (t >= d) ? part[t - d] : 0;
        __syncthreads();
        part[t] += add;
        __syncthreads();
    }
    int base = part[t] - s;   // exclusive
    for (int i = lo; i < hi; i++) {
        off[i] = base; cur[i] = base;
        base += cnt[i];
    }
    if (t == 0) off[n] = part[1023];
}

__global__ void dinv_kernel(const float* __restrict__ deg, float* __restrict__ dinv, int n) {
    int i = blockIdx.x * blockDim.x + threadIdx.x;
    if (i < n) {
        float d = deg[i];
        dinv[i] = (d > 0.0f) ? rsqrtf(d) : 0.0f;
    }
}

__global__ void fill_kernel(const int* __restrict__ row, const int* __restrict__ col,
                            const float* __restrict__ w, const float* __restrict__ dinv,
                            int* cur, int* __restrict__ srcs,
                            float* __restrict__ wpl, float* __restrict__ wnd, int e) {
    int i = blockIdx.x * blockDim.x + threadIdx.x;
    if (i >= e) return;
    int r = row[i];
    float ww = w[i];
    int pos = atomicAdd(cur + col[i], 1);
    srcs[pos] = r;
    wpl[pos]  = ww;
    wnd[pos]  = ww * __ldg(dinv + r);
}

// Wc[k,f] = sum_j Wg[layer][k][j] * Wih[f][j]   (Wc : [64,192])
__global__ void wc_kernel(const float* __restrict__ Wg, const float* __restrict__ Wih,
                          float* __restrict__ Wc) {
    int idx = blockIdx.x * blockDim.x + threadIdx.x;   // 64*192
    if (idx >= 64 * 192) return;
    int k = idx / 192, f = idx % 192;
    float s = 0.0f;
#pragma unroll 8
    for (int j = 0; j < 64; j++) s = fmaf(Wg[k * 64 + j], Wih[f * 64 + j], s);
    Wc[idx] = s;
}

// ---------------- CSR gather (F=64), fused epilogues -------------------------
// EPI 0: plain weighted sum -> dst            (GGC message aggregation)
// EPI 1: GCN1: relu(dinv*acc + dinv^2*self + bias) -> dst
template<int EPI>
__global__ __launch_bounds__(256)
void gather64_kernel(const float* __restrict__ feat, const float* __restrict__ selff,
                     float* __restrict__ dst,
                     const int* __restrict__ off, const int* __restrict__ srcs,
                     const float* __restrict__ ew, const float* __restrict__ dinv,
                     const float* __restrict__ bias, int n) {
    int node = (blockIdx.x * blockDim.x + threadIdx.x) >> 5;
    if (node >= n) return;
    int lane = threadIdx.x & 31;
    int h = lane >> 4;        // 0/1 : which edge of the pair
    int l = lane & 15;        // float4 lane within the 64-dim row

    int beg = __ldg(off + node);
    int end = __ldg(off + node + 1);

    float4 a0 = make_float4(0.f, 0.f, 0.f, 0.f);
    float4 a1 = make_float4(0.f, 0.f, 0.f, 0.f);

    int j = beg + h;
    for (; j + 2 < end; j += 4) {
        int   s0 = __ldg(srcs + j);
        float w0 = __ldg(ew + j);
        int   s1 = __ldg(srcs + j + 2);
        float w1 = __ldg(ew + j + 2);
        float4 v0 = *reinterpret_cast<const float4*>(feat + (size_t)s0 * 64 + l * 4);
        float4 v1 = *reinterpret_cast<const float4*>(feat + (size_t)s1 * 64 + l * 4);
        a0.x = fmaf(w0, v0.x, a0.x); a0.y = fmaf(w0, v0.y, a0.y);
        a0.z = fmaf(w0, v0.z, a0.z); a0.w = fmaf(w0, v0.w, a0.w);
        a1.x = fmaf(w1, v1.x, a1.x); a1.y = fmaf(w1, v1.y, a1.y);
        a1.z = fmaf(w1, v1.z, a1.z); a1.w = fmaf(w1, v1.w, a1.w);
    }
    for (; j < end; j += 2) {
        int   s0 = __ldg(srcs + j);
        float w0 = __ldg(ew + j);
        float4 v0 = *reinterpret_cast<const float4*>(feat + (size_t)s0 * 64 + l * 4);
        a0.x = fmaf(w0, v0.x, a0.x); a0.y = fmaf(w0, v0.y, a0.y);
        a0.z = fmaf(w0, v0.z, a0.z); a0.w = fmaf(w0, v0.w, a0.w);
    }
    a0.x += a1.x; a0.y += a1.y; a0.z += a1.z; a0.w += a1.w;

    // combine the two half-warp partial sums
    a0.x += __shfl_down_sync(0xffffffffu, a0.x, 16);
    a0.y += __shfl_down_sync(0xffffffffu, a0.y, 16);
    a0.z += __shfl_down_sync(0xffffffffu, a0.z, 16);
    a0.w += __shfl_down_sync(0xffffffffu, a0.w, 16);

    if (h == 0) {
        float4 o;
        if (EPI == 1) {
            float di = __ldg(dinv + node);
            float4 sv = *reinterpret_cast<const float4*>(selff + (size_t)node * 64 + l * 4);
            float4 bv = *reinterpret_cast<const float4*>(bias + l * 4);
            o.x = fmaxf(fmaf(di, a0.x, fmaf(di * di, sv.x, bv.x)), 0.0f);
            o.y = fmaxf(fmaf(di, a0.y, fmaf(di * di, sv.y, bv.y)), 0.0f);
            o.z = fmaxf(fmaf(di, a0.z, fmaf(di * di, sv.z, bv.z)), 0.0f);
            o.w = fmaxf(fmaf(di, a0.w, fmaf(di * di, sv.w, bv.w)), 0.0f);
        } else {
            o = a0;
        }
        *reinterpret_cast<float4*>(dst + (size_t)node * 64 + l * 4) = o;
    }
}

// ---------------- CSR gather (F=16) + GCN epilogue + log_softmax --------------
__global__ __launch_bounds__(256)
void gather16_lsm_kernel(const float* __restrict__ feat, float* __restrict__ out,
                         const int* __restrict__ off, const int* __restrict__ srcs,
                         const float* __restrict__ ew, const float* __restrict__ dinv,
                         const float* __restrict__ b2, int n) {
    int node = (blockIdx.x * blockDim.x + threadIdx.x) >> 5;
    if (node >= n) return;
    int lane = threadIdx.x & 31;
    int h = lane >> 2;        // 0..7 : edge slot
    int l = lane & 3;         // float4 lane within 16-dim row

    int beg = __ldg(off + node);
    int end = __ldg(off + node + 1);

    float4 a = make_float4(0.f, 0.f, 0.f, 0.f);
    for (int j = beg + h; j < end; j += 8) {
        int   s0 = __ldg(srcs + j);
        float w0 = __ldg(ew + j);
        float4 v = *reinterpret_cast<const float4*>(feat + (size_t)s0 * 16 + l * 4);
        a.x = fmaf(w0, v.x, a.x); a.y = fmaf(w0, v.y, a.y);
        a.z = fmaf(w0, v.z, a.z); a.w = fmaf(w0, v.w, a.w);
    }
#pragma unroll
    for (int o = 16; o >= 4; o >>= 1) {
        a.x += __shfl_down_sync(0xffffffffu, a.x, o);
        a.y += __shfl_down_sync(0xffffffffu, a.y, o);
        a.z += __shfl_down_sync(0xffffffffu, a.z, o);
        a.w += __shfl_down_sync(0xffffffffu, a.w, o);
    }

    if (h == 0) {   // lanes 0..3 hold the full 16-dim row
        float di = __ldg(dinv + node);
        float4 sv = *reinterpret_cast<const float4*>(feat + (size_t)node * 16 + l * 4);
        float4 bv = *reinterpret_cast<const float4*>(b2 + l * 4);
        float4 v;
        v.x = fmaf(di, a.x, fmaf(di * di, sv.x, bv.x));
        v.y = fmaf(di, a.y, fmaf(di * di, sv.y, bv.y));
        v.z = fmaf(di, a.z, fmaf(di * di, sv.z, bv.z));
        v.w = fmaf(di, a.w, fmaf(di * di, sv.w, bv.w));
        // log_softmax across the 16 values held by lanes 0..3
        float mx = fmaxf(fmaxf(v.x, v.y), fmaxf(v.z, v.w));
        mx = fmaxf(mx, __shfl_xor_sync(0x0000000Fu, mx, 1));
        mx = fmaxf(mx, __shfl_xor_sync(0x0000000Fu, mx, 2));
        float se = expf(v.x - mx) + expf(v.y - mx) + expf(v.z - mx) + expf(v.w - mx);
        se += __shfl_xor_sync(0x0000000Fu, se, 1);
        se += __shfl_xor_sync(0x0000000Fu, se, 2);
        float lse = mx + logf(se);
        float4 o;
        o.x = v.x - lse; o.y = v.y - lse; o.z = v.z - lse; o.w = v.w - lse;
        *reinterpret_cast<float4*>(out + (size_t)node * 16 + l * 4) = o;
    }
}

// ---------------- register-tiled fp32 GEMM -----------------------------------
template<int BM, int BN, int BK, int TM, int TN, bool TRANSB>
__global__ __launch_bounds__((BM/TM)*(BN/TN))
void gemm_kernel(const float* __restrict__ A, const float* __restrict__ B,
                 float* __restrict__ C, int M, int K, int Nb) {
    constexpr int NT  = (BM / TM) * (BN / TN);
    constexpr int BMP = BM + 4;
    constexpr int BNP = BN + 4;
    __shared__ float As[BK][BMP];
    __shared__ float Bs[BK][BNP];

    const int tid = threadIdx.x;
    const int tr  = tid / (BN / TN);
    const int tc  = tid % (BN / TN);
    const int cm  = blockIdx.x * BM;
    const int cn  = blockIdx.y * BN;

    float acc[TM][TN];
#pragma unroll
    for (int i = 0; i < TM; i++)
#pragma unroll
        for (int j = 0; j < TN; j++) acc[i][j] = 0.0f;

    for (int k0 = 0; k0 < K; k0 += BK) {
#pragma unroll
        for (int s = tid; s < BM * BK / 4; s += NT) {
            int arow = s / (BK / 4);
            int ac4  = s % (BK / 4);
            float4 v = make_float4(0.f, 0.f, 0.f, 0.f);
            int gr = cm + arow;
            if (gr < M)
                v = *reinterpret_cast<const float4*>(A + (size_t)gr * K + k0 + ac4 * 4);
            As[ac4 * 4 + 0][arow] = v.x;
            As[ac4 * 4 + 1][arow] = v.y;
            As[ac4 * 4 + 2][arow] = v.z;
            As[ac4 * 4 + 3][arow] = v.w;
        }
        if (!TRANSB) {
#pragma unroll
            for (int s = tid; s < BK * BN / 4; s += NT) {
                int brow = s / (BN / 4);
                int bc4  = s % (BN / 4);
                float4 v = *reinterpret_cast<const float4*>(
                    B + (size_t)(k0 + brow) * Nb + cn + bc4 * 4);
                Bs[brow][bc4 * 4 + 0] = v.x;
                Bs[brow][bc4 * 4 + 1] = v.y;
                Bs[brow][bc4 * 4 + 2] = v.z;
                Bs[brow][bc4 * 4 + 3] = v.w;
            }
        } else {
#pragma unroll
            for (int s = tid; s < BK * BN; s += NT) {
                int kk = s % BK;
                int nn = s / BK;
                Bs[kk][nn] = B[(size_t)(cn + nn) * K + k0 + kk];
            }
        }
        __syncthreads();

#pragma unroll
        for (int kk = 0; kk < BK; kk++) {
            float a[TM], b[TN];
#pragma unroll
            for (int i = 0; i < TM; i++) a[i] = As[kk][tr * TM + i];
#pragma unroll
            for (int j = 0; j < TN; j++) b[j] = Bs[kk][tc * TN + j];
#pragma unroll
            for (int i = 0; i < TM; i++)
#pragma unroll
                for (int j = 0; j < TN; j++) acc[i][j] = fmaf(a[i], b[j], acc[i][j]);
        }
        __syncthreads();
    }

#pragma unroll
    for (int i = 0; i < TM; i++) {
        int gr = cm + tr * TM + i;
        if (gr < M) {
            float4 v = make_float4(acc[i][0], acc[i][1], acc[i][2], acc[i][3]);
            *reinterpret_cast<float4*>(C + (size_t)gr * Nb + cn + tc * TN) = v;
        }
    }
}

// ---------------- GRU + small kernels -----------------------------------------
__global__ void gru_kernel(const float* __restrict__ gi, const float* __restrict__ gh,
                           const float* __restrict__ bih, const float* __restrict__ bhh,
                           float* __restrict__ s, int n) {
    int idx = blockIdx.x * blockDim.x + threadIdx.x;
    if (idx >= n * 64) return;
    int i = idx >> 6;
    int f = idx & 63;
    size_t base = (size_t)i * 192 + f;
    float ir = gi[base]       + bih[f];
    float iz = gi[base + 64]  + bih[64 + f];
    float in_= gi[base + 128] + bih[128 + f];
    float hr = gh[base]       + bhh[f];
    float hz = gh[base + 64]  + bhh[64 + f];
    float hn = gh[base + 128] + bhh[128 + f];
    float r  = sigmoidf_(ir + hr);
    float z  = sigmoidf_(iz + hz);
    float ng = tanhf(in_ + r * hn);
    s[idx] = (1.0f - z) * ng + z * s[idx];
}

// t2 = s @ W2 [N,16]
__global__ void w2_kernel(const float* __restrict__ s, const float* __restrict__ W2,
                          float* __restrict__ t2, int n) {
    __shared__ float Wsm[64 * 16];
    for (int i = threadIdx.x; i < 64 * 16; i += blockDim.x) Wsm[i] = W2[i];
    __syncthreads();
    int node = blockIdx.x * 16 + threadIdx.x / 16;
    int c = threadIdx.x & 15;
    if (node >= n) return;
    const float4* srow = reinterpret_cast<const float4*>(s + (size_t)node * 64);
    float acc = 0.0f;
#pragma unroll
    for (int k4 = 0; k4 < 16; k4++) {
        float4 sv = __ldg(srow + k4);
        acc = fmaf(sv.x, Wsm[(k4 * 4 + 0) * 16 + c], acc);
        acc = fmaf(sv.y, Wsm[(k4 * 4 + 1) * 16 + c], acc);
        acc = fmaf(sv.z, Wsm[(k4 * 4 + 2) * 16 + c], acc);
        acc = fmaf(sv.w, Wsm[(k4 * 4 + 3) * 16 + c], acc);
    }
    t2[(size_t)node * 16 + c] = acc;
}

// ---------------- launch -------------------------------------------------------
extern "C" void kernel_launch(void* const* d_in, const int* in_sizes, int n_in,
                              void* d_out, int out_size) {
    const float* x   = (const float*)d_in[0];
    const int*   ei  = (const int*)  d_in[1];
    const float* ew  = (const float*)d_in[2];
    const float* W1  = (const float*)d_in[3];
    const float* b1  = (const float*)d_in[4];
    const float* Wg  = (const float*)d_in[5];
    const float* Wih = (const float*)d_in[6];
    const float* Whh = (const float*)d_in[7];
    const float* bih = (const float*)d_in[8];
    const float* bhh = (const float*)d_in[9];
    const float* W2  = (const float*)d_in[10];
    const float* b2  = (const float*)d_in[11];
    float* out = (float*)d_out;

    const int n = in_sizes[0] / 512;
    const int e = in_sizes[2];
    const int* row = ei;
    const int* col = ei + e;

    float *deg, *dinv, *t1, *s, *u, *gi, *gh, *t2, *wpl, *wnd, *wc;
    int *off, *cur, *srcs;
    cudaGetSymbolAddress((void**)&deg,  g_deg);
    cudaGetSymbolAddress((void**)&dinv, g_dinv);
    cudaGetSymbolAddress((void**)&t1,   g_t1);
    cudaGetSymbolAddress((void**)&s,    g_s);
    cudaGetSymbolAddress((void**)&u,    g_u);
    cudaGetSymbolAddress((void**)&gi,   g_gi);
    cudaGetSymbolAddress((void**)&gh,   g_gh);
    cudaGetSymbolAddress((void**)&t2,   g_t2);
    cudaGetSymbolAddress((void**)&off,  g_off);
    cudaGetSymbolAddress((void**)&cur,  g_cur);
    cudaGetSymbolAddress((void**)&srcs, g_srcs);
    cudaGetSymbolAddress((void**)&wpl,  g_wpl);
    cudaGetSymbolAddress((void**)&wnd,  g_wnd);
    cudaGetSymbolAddress((void**)&wc,   g_wc);

    const int TB = 256;
    const int mblocks = (n + 127) / 128;
    const int gblocks = (n + 7) / 8;       // 8 warps/block, 1 node/warp

    // ---- CSR build + shared gcn_norm ----
    init_kernel<<<(n + TB - 1) / TB, TB>>>(deg, cur, n);
    count_kernel<<<(e + TB - 1) / TB, TB>>>(col, ew, cur, deg, e);
    scan_kernel<<<1, 1024>>>(cur, off, cur, n);   // note: reads cur(counts) chunk-locally before overwrite
    dinv_kernel<<<(n + TB - 1) / TB, TB>>>(deg, dinv, n);
    fill_kernel<<<(e + TB - 1) / TB, TB>>>(row, col, ew, dinv, cur, srcs, wpl, wnd, e);

    // combined GGC weights (independent of graph)
    wc_kernel<<<(64 * 192 + TB - 1) / TB, TB>>>(Wg,            Wih, wc);
    wc_kernel<<<(64 * 192 + TB - 1) / TB, TB>>>(Wg + 64 * 64,  Wih, wc + 64 * 192);

    // ---- GCN conv 1 ----
    gemm_kernel<128, 64, 16, 8, 4, false><<<dim3(mblocks, 1), 256>>>(x, W1, t1, n, 512, 64);
    gather64_kernel<1><<<gblocks, 256>>>(t1, t1, s, off, srcs, wnd, dinv, b1, n);

    // ---- GatedGraphConv (2 layers) ----
    for (int layer = 0; layer < 2; layer++) {
        gather64_kernel<0><<<gblocks, 256>>>(s, s, u, off, srcs, wpl, dinv, b1, n);
        gemm_kernel<128, 64, 16, 8, 4, false><<<dim3(mblocks, 3), 256>>>(
            u, wc + (size_t)layer * 64 * 192, gi, n, 64, 192);
        gemm_kernel<128, 64, 16, 8, 4, true><<<dim3(mblocks, 3), 256>>>(s, Whh, gh, n, 64, 192);
        gru_kernel<<<(n * 64 + TB - 1) / TB, TB>>>(gi, gh, bih, bhh, s, n);
    }

    // ---- GCN conv 2 + log_softmax ----
    w2_kernel<<<(n + 15) / 16, 256>>>(s, W2, t2, n);
    gather16_lsm_kernel<<<gblocks, 256>>>(t2, out, off, srcs, wnd, dinv, b2, n);
}

// round 3
// speedup vs baseline: 1.4003x; 1.1267x over previous
#include <cuda_runtime.h>
#include <cstdint>

#define MAXN 100000
#define MAXE 3200000

// ---------------- scratch (device globals) ----------------------------------
__device__ float g_deg [MAXN];
__device__ float g_dinv[MAXN];
__device__ float g_t1  [MAXN * 64];   // x@W1
__device__ float g_s   [MAXN * 64];   // node state
__device__ float g_u   [MAXN * 64];   // gathered state (GGC)
__device__ float g_t2  [MAXN * 16];   // s@W2
// CSR
__device__ int   g_off [MAXN + 1];
__device__ int   g_cur [MAXN];
__device__ int   g_srcs[MAXE];
__device__ float g_wpl [MAXE];        // plain w   (GGC)
__device__ float g_wnd [MAXE];        // w * dinv[src] (GCN)
__device__ float g_wc  [2 * 64 * 192]; // Wg@Wih^T per layer  [k][f]
__device__ float g_whht[64 * 192];     // Whh^T               [k][f]

typedef unsigned long long ull;

__device__ __forceinline__ float sigmoidf_(float x) { return 1.0f / (1.0f + expf(-x)); }

// ---- packed f32x2 helpers ---------------------------------------------------
__device__ __forceinline__ ull dup2(float a) {
    ull r; asm("mov.b64 %0,{%1,%1};" : "=l"(r) : "f"(a)); return r;
}
__device__ __forceinline__ void fma2(ull& d, ull a, ull b) {
    asm("fma.rn.f32x2 %0,%1,%2,%0;" : "+l"(d) : "l"(a), "l"(b));
}
__device__ __forceinline__ float2 unpk(ull v) {
    float2 f; asm("mov.b64 {%0,%1},%2;" : "=f"(f.x), "=f"(f.y) : "l"(v)); return f;
}

// ---------------- CSR build --------------------------------------------------
__global__ void init_kernel(float* deg, int* cnt, int n) {
    int i = blockIdx.x * blockDim.x + threadIdx.x;
    if (i < n) { deg[i] = 1.0f; cnt[i] = 0; }
}

__global__ void count_kernel(const int* __restrict__ col, const float* __restrict__ w,
                             int* cnt, float* deg, int e) {
    int i = blockIdx.x * blockDim.x + threadIdx.x;
    if (i < e) {
        int c = col[i];
        atomicAdd(cnt + c, 1);
        atomicAdd(deg + c, w[i]);
    }
}

__global__ void scan_kernel(const int* __restrict__ cnt, int* __restrict__ off,
                            int* __restrict__ cur, int n) {
    __shared__ int part[1024];
    int t = threadIdx.x;
    int chunk = (n + 1023) >> 10;
    int lo = t * chunk;
    int hi = min(lo + chunk, n);
    int s = 0;
    for (int i = lo; i < hi; i++) s += cnt[i];
    part[t] = s;
    __syncthreads();
    for (int d = 1; d < 1024; d <<= 1) {
        int add = (t >= d) ? part[t - d] : 0;
        __syncthreads();
        part[t] += add;
        __syncthreads();
    }
    int base = part[t] - s;   // exclusive
    for (int i = lo; i < hi; i++) {
        int c = cnt[i];       // read BEFORE cur[i] store (cnt may alias cur)
        off[i] = base; cur[i] = base;
        base += c;
    }
    if (t == 0) off[n] = part[1023];
}

__global__ void dinv_kernel(const float* __restrict__ deg, float* __restrict__ dinv, int n) {
    int i = blockIdx.x * blockDim.x + threadIdx.x;
    if (i < n) {
        float d = deg[i];
        dinv[i] = (d > 0.0f) ? rsqrtf(d) : 0.0f;
    }
}

__global__ void fill_kernel(const int* __restrict__ row, const int* __restrict__ col,
                            const float* __restrict__ w, const float* __restrict__ dinv,
                            int* cur, int* __restrict__ srcs,
                            float* __restrict__ wpl, float* __restrict__ wnd, int e) {
    int i = blockIdx.x * blockDim.x + threadIdx.x;
    if (i >= e) return;
    int r = row[i];
    float ww = w[i];
    int pos = atomicAdd(cur + col[i], 1);
    srcs[pos] = r;
    wpl[pos]  = ww;
    wnd[pos]  = ww * __ldg(dinv + r);
}

// Wc[k,f] = sum_j Wg[layer][k][j] * Wih[f][j]   (Wc : [64,192])
__global__ void wc_kernel(const float* __restrict__ Wg, const float* __restrict__ Wih,
                          float* __restrict__ Wc) {
    int idx = blockIdx.x * blockDim.x + threadIdx.x;
    if (idx >= 64 * 192) return;
    int k = idx / 192, f = idx % 192;
    float s = 0.0f;
#pragma unroll 8
    for (int j = 0; j < 64; j++) s = fmaf(Wg[k * 64 + j], Wih[f * 64 + j], s);
    Wc[idx] = s;
}

// WhhT[k][f] = Whh[f][k]
__global__ void whht_kernel(const float* __restrict__ Whh, float* __restrict__ WhhT) {
    int idx = blockIdx.x * blockDim.x + threadIdx.x;
    if (idx >= 64 * 192) return;
    int k = idx / 192, f = idx % 192;
    WhhT[idx] = Whh[f * 64 + k];
}

// ---------------- CSR gather (F=64), fused epilogues -------------------------
template<int EPI>
__global__ __launch_bounds__(256)
void gather64_kernel(const float* __restrict__ feat, const float* __restrict__ selff,
                     float* __restrict__ dst,
                     const int* __restrict__ off, const int* __restrict__ srcs,
                     const float* __restrict__ ew, const float* __restrict__ dinv,
                     const float* __restrict__ bias, int n) {
    int node = (blockIdx.x * blockDim.x + threadIdx.x) >> 5;
    if (node >= n) return;
    int lane = threadIdx.x & 31;
    int h = lane >> 4;
    int l = lane & 15;

    int beg = __ldg(off + node);
    int end = __ldg(off + node + 1);

    float4 a0 = make_float4(0.f, 0.f, 0.f, 0.f);
    float4 a1 = make_float4(0.f, 0.f, 0.f, 0.f);

    int j = beg + h;
    for (; j + 2 < end; j += 4) {
        int   s0 = __ldg(srcs + j);
        float w0 = __ldg(ew + j);
        int   s1 = __ldg(srcs + j + 2);
        float w1 = __ldg(ew + j + 2);
        float4 v0 = *reinterpret_cast<const float4*>(feat + (size_t)s0 * 64 + l * 4);
        float4 v1 = *reinterpret_cast<const float4*>(feat + (size_t)s1 * 64 + l * 4);
        a0.x = fmaf(w0, v0.x, a0.x); a0.y = fmaf(w0, v0.y, a0.y);
        a0.z = fmaf(w0, v0.z, a0.z); a0.w = fmaf(w0, v0.w, a0.w);
        a1.x = fmaf(w1, v1.x, a1.x); a1.y = fmaf(w1, v1.y, a1.y);
        a1.z = fmaf(w1, v1.z, a1.z); a1.w = fmaf(w1, v1.w, a1.w);
    }
    for (; j < end; j += 2) {
        int   s0 = __ldg(srcs + j);
        float w0 = __ldg(ew + j);
        float4 v0 = *reinterpret_cast<const float4*>(feat + (size_t)s0 * 64 + l * 4);
        a0.x = fmaf(w0, v0.x, a0.x); a0.y = fmaf(w0, v0.y, a0.y);
        a0.z = fmaf(w0, v0.z, a0.z); a0.w = fmaf(w0, v0.w, a0.w);
    }
    a0.x += a1.x; a0.y += a1.y; a0.z += a1.z; a0.w += a1.w;

    a0.x += __shfl_down_sync(0xffffffffu, a0.x, 16);
    a0.y += __shfl_down_sync(0xffffffffu, a0.y, 16);
    a0.z += __shfl_down_sync(0xffffffffu, a0.z, 16);
    a0.w += __shfl_down_sync(0xffffffffu, a0.w, 16);

    if (h == 0) {
        float4 o;
        if (EPI == 1) {
            float di = __ldg(dinv + node);
            float4 sv = *reinterpret_cast<const float4*>(selff + (size_t)node * 64 + l * 4);
            float4 bv = *reinterpret_cast<const float4*>(bias + l * 4);
            o.x = fmaxf(fmaf(di, a0.x, fmaf(di * di, sv.x, bv.x)), 0.0f);
            o.y = fmaxf(fmaf(di, a0.y, fmaf(di * di, sv.y, bv.y)), 0.0f);
            o.z = fmaxf(fmaf(di, a0.z, fmaf(di * di, sv.z, bv.z)), 0.0f);
            o.w = fmaxf(fmaf(di, a0.w, fmaf(di * di, sv.w, bv.w)), 0.0f);
        } else {
            o = a0;
        }
        *reinterpret_cast<float4*>(dst + (size_t)node * 64 + l * 4) = o;
    }
}

// ---------------- CSR gather (F=16) + GCN epilogue + log_softmax --------------
__global__ __launch_bounds__(256)
void gather16_lsm_kernel(const float* __restrict__ feat, float* __restrict__ out,
                         const int* __restrict__ off, const int* __restrict__ srcs,
                         const float* __restrict__ ew, const float* __restrict__ dinv,
                         const float* __restrict__ b2, int n) {
    int node = (blockIdx.x * blockDim.x + threadIdx.x) >> 5;
    if (node >= n) return;
    int lane = threadIdx.x & 31;
    int h = lane >> 2;
    int l = lane & 3;

    int beg = __ldg(off + node);
    int end = __ldg(off + node + 1);

    float4 a = make_float4(0.f, 0.f, 0.f, 0.f);
    for (int j = beg + h; j < end; j += 8) {
        int   s0 = __ldg(srcs + j);
        float w0 = __ldg(ew + j);
        float4 v = *reinterpret_cast<const float4*>(feat + (size_t)s0 * 16 + l * 4);
        a.x = fmaf(w0, v.x, a.x); a.y = fmaf(w0, v.y, a.y);
        a.z = fmaf(w0, v.z, a.z); a.w = fmaf(w0, v.w, a.w);
    }
#pragma unroll
    for (int o = 16; o >= 4; o >>= 1) {
        a.x += __shfl_down_sync(0xffffffffu, a.x, o);
        a.y += __shfl_down_sync(0xffffffffu, a.y, o);
        a.z += __shfl_down_sync(0xffffffffu, a.z, o);
        a.w += __shfl_down_sync(0xffffffffu, a.w, o);
    }

    if (h == 0) {
        float di = __ldg(dinv + node);
        float4 sv = *reinterpret_cast<const float4*>(feat + (size_t)node * 16 + l * 4);
        float4 bv = *reinterpret_cast<const float4*>(b2 + l * 4);
        float4 v;
        v.x = fmaf(di, a.x, fmaf(di * di, sv.x, bv.x));
        v.y = fmaf(di, a.y, fmaf(di * di, sv.y, bv.y));
        v.z = fmaf(di, a.z, fmaf(di * di, sv.z, bv.z));
        v.w = fmaf(di, a.w, fmaf(di * di, sv.w, bv.w));
        float mx = fmaxf(fmaxf(v.x, v.y), fmaxf(v.z, v.w));
        mx = fmaxf(mx, __shfl_xor_sync(0x0000000Fu, mx, 1));
        mx = fmaxf(mx, __shfl_xor_sync(0x0000000Fu, mx, 2));
        float se = expf(v.x - mx) + expf(v.y - mx) + expf(v.z - mx) + expf(v.w - mx);
        se += __shfl_xor_sync(0x0000000Fu, se, 1);
        se += __shfl_xor_sync(0x0000000Fu, se, 2);
        float lse = mx + logf(se);
        float4 o;
        o.x = v.x - lse; o.y = v.y - lse; o.z = v.z - lse; o.w = v.w - lse;
        *reinterpret_cast<float4*>(out + (size_t)node * 16 + l * 4) = o;
    }
}

// ---------------- register-tiled fp32 GEMM with packed FFMA2 ------------------
// C[M,Nb] = A[M,K] @ B[K,Nb]
template<int BM, int BN, int BK, int TM, int TN>
__global__ __launch_bounds__((BM/TM)*(BN/TN))
void gemm_kernel(const float* __restrict__ A, const float* __restrict__ B,
                 float* __restrict__ C, int M, int K, int Nb) {
    constexpr int NT  = (BM / TM) * (BN / TN);
    constexpr int BMP = BM + 4;
    constexpr int BNP = BN + 4;
    __shared__ __align__(16) float As[BK][BMP];
    __shared__ __align__(16) float Bs[BK][BNP];

    const int tid = threadIdx.x;
    const int tr  = tid / (BN / TN);
    const int tc  = tid % (BN / TN);
    const int cm  = blockIdx.x * BM;
    const int cn  = blockIdx.y * BN;

    ull acc2[TM][TN / 2];
#pragma unroll
    for (int i = 0; i < TM; i++)
#pragma unroll
        for (int j = 0; j < TN / 2; j++) acc2[i][j] = 0ULL;

    for (int k0 = 0; k0 < K; k0 += BK) {
#pragma unroll
        for (int s = tid; s < BM * BK / 4; s += NT) {
            int arow = s / (BK / 4);
            int ac4  = s % (BK / 4);
            float4 v = make_float4(0.f, 0.f, 0.f, 0.f);
            int gr = cm + arow;
            if (gr < M)
                v = *reinterpret_cast<const float4*>(A + (size_t)gr * K + k0 + ac4 * 4);
            As[ac4 * 4 + 0][arow] = v.x;
            As[ac4 * 4 + 1][arow] = v.y;
            As[ac4 * 4 + 2][arow] = v.z;
            As[ac4 * 4 + 3][arow] = v.w;
        }
#pragma unroll
        for (int s = tid; s < BK * BN / 4; s += NT) {
            int brow = s / (BN / 4);
            int bc4  = s % (BN / 4);
            float4 v = *reinterpret_cast<const float4*>(
                B + (size_t)(k0 + brow) * Nb + cn + bc4 * 4);
            Bs[brow][bc4 * 4 + 0] = v.x;
            Bs[brow][bc4 * 4 + 1] = v.y;
            Bs[brow][bc4 * 4 + 2] = v.z;
            Bs[brow][bc4 * 4 + 3] = v.w;
        }
        __syncthreads();

#pragma unroll
        for (int kk = 0; kk < BK; kk++) {
            ull a2[TM], b2[TN / 2];
#pragma unroll
            for (int i = 0; i < TM; i++) a2[i] = dup2(As[kk][tr * TM + i]);
#pragma unroll
            for (int j = 0; j < TN / 2; j++)
                b2[j] = *reinterpret_cast<const ull*>(&Bs[kk][tc * TN + 2 * j]);
#pragma unroll
            for (int i = 0; i < TM; i++)
#pragma unroll
                for (int j = 0; j < TN / 2; j++) fma2(acc2[i][j], a2[i], b2[j]);
        }
        __syncthreads();
    }

#pragma unroll
    for (int i = 0; i < TM; i++) {
        int gr = cm + tr * TM + i;
        if (gr < M) {
            float2 p0 = unpk(acc2[i][0]);
            float2 p1 = unpk(acc2[i][1]);
            float4 v = make_float4(p0.x, p0.y, p1.x, p1.y);
            *reinterpret_cast<float4*>(C + (size_t)gr * Nb + cn + tc * TN) = v;
        }
    }
}

// ---------------- fused GGC layer: gi/gh GEMMs + GRU --------------------------
// Per 64-node block:
//   phase 0: At <- u tile, Wt <- Wc     ; accumulate r,z,i_n
//   phase 1: At <- s tile, Wt <- WhhT   ; accumulate r,z,h_n
//   epilogue: GRU, write s in place (old s read from At)
__global__ __launch_bounds__(256)
void ggc_fused_kernel(const float* __restrict__ u, float* __restrict__ s,
                      const float* __restrict__ Wc, const float* __restrict__ WhhT,
                      const float* __restrict__ bih, const float* __restrict__ bhh,
                      int n) {
    extern __shared__ __align__(16) float smem[];
    float* Wt = smem;               // [64][192]
    float* At = smem + 64 * 192;    // [64][72]  (k-major, node minor)

    const int tid = threadIdx.x;
    const int tr  = tid >> 4;       // 0..15 node group
    const int tc  = tid & 15;       // 0..15 f group (f = tc*4 + j)
    const int nodebase = blockIdx.x * 64;

    ull ar[4][2], az[4][2], an[4][2], ah[4][2];
#pragma unroll
    for (int i = 0; i < 4; i++)
#pragma unroll
        for (int j = 0; j < 2; j++) { ar[i][j] = 0; az[i][j] = 0; an[i][j] = 0; ah[i][j] = 0; }

#pragma unroll
    for (int phase = 0; phase < 2; phase++) {
        const float* W = (phase == 0) ? Wc : WhhT;
        const float* A = (phase == 0) ? u  : s;
        // load weights [64][192]
        for (int i = tid; i < 64 * 192 / 4; i += 256)
            *reinterpret_cast<float4*>(Wt + i * 4) =
                *reinterpret_cast<const float4*>(W + i * 4);
        // load A tile transposed: At[k][node_local]
        {
            int nl = tid >> 2;             // 0..63 node local
            int kb = (tid & 3) * 16;       // k segment
            int gn = nodebase + nl;
#pragma unroll
            for (int q = 0; q < 4; q++) {
                float4 v = make_float4(0.f, 0.f, 0.f, 0.f);
                if (gn < n)
                    v = *reinterpret_cast<const float4*>(A + (size_t)gn * 64 + kb + q * 4);
                At[(kb + q * 4 + 0) * 72 + nl] = v.x;
                At[(kb + q * 4 + 1) * 72 + nl] = v.y;
                At[(kb + q * 4 + 2) * 72 + nl] = v.z;
                At[(kb + q * 4 + 3) * 72 + nl] = v.w;
            }
        }
        __syncthreads();

#pragma unroll 4
        for (int k = 0; k < 64; k++) {
            ull a2[4];
#pragma unroll
            for (int i = 0; i < 4; i++) a2[i] = dup2(At[k * 72 + tr * 4 + i]);
            const float* wr = Wt + k * 192 + tc * 4;
            ull wr2[2], wz2[2], wn2[2];
#pragma unroll
            for (int j = 0; j < 2; j++) {
                wr2[j] = *reinterpret_cast<const ull*>(wr + 2 * j);
                wz2[j] = *reinterpret_cast<const ull*>(wr + 64 + 2 * j);
                wn2[j] = *reinterpret_cast<const ull*>(wr + 128 + 2 * j);
            }
            if (phase == 0) {
#pragma unroll
                for (int i = 0; i < 4; i++)
#pragma unroll
                    for (int j = 0; j < 2; j++) {
                        fma2(ar[i][j], a2[i], wr2[j]);
                        fma2(az[i][j], a2[i], wz2[j]);
                        fma2(an[i][j], a2[i], wn2[j]);
                    }
            } else {
#pragma unroll
                for (int i = 0; i < 4; i++)
#pragma unroll
                    for (int j = 0; j < 2; j++) {
                        fma2(ar[i][j], a2[i], wr2[j]);
                        fma2(az[i][j], a2[i], wz2[j]);
                        fma2(ah[i][j], a2[i], wn2[j]);
                    }
            }
        }
        if (phase == 0) __syncthreads();   // before overwriting Wt/At
    }

    // epilogue: GRU.  At holds the s tile (k-major).
    const int fb = tc * 4;
    float br[4], bz[4], bn_[4], bh_[4];
#pragma unroll
    for (int j = 0; j < 4; j++) {
        br[j]  = __ldg(bih + fb + j)       + __ldg(bhh + fb + j);
        bz[j]  = __ldg(bih + 64 + fb + j)  + __ldg(bhh + 64 + fb + j);
        bn_[j] = __ldg(bih + 128 + fb + j);
        bh_[j] = __ldg(bhh + 128 + fb + j);
    }
#pragma unroll
    for (int i = 0; i < 4; i++) {
        int nl = tr * 4 + i;
        int gn = nodebase + nl;
        if (gn >= n) continue;
        float out4[4];
#pragma unroll
        for (int j2 = 0; j2 < 2; j2++) {
            float2 rv = unpk(ar[i][j2]);
            float2 zv = unpk(az[i][j2]);
            float2 nv = unpk(an[i][j2]);
            float2 hv = unpk(ah[i][j2]);
#pragma unroll
            for (int l = 0; l < 2; l++) {
                int j = j2 * 2 + l;
                float rr = sigmoidf_((l ? rv.y : rv.x) + br[j]);
                float zz = sigmoidf_((l ? zv.y : zv.x) + bz[j]);
                float in_ = (l ? nv.y : nv.x) + bn_[j];
                float hn  = (l ? hv.y : hv.x) + bh_[j];
                float ng = tanhf(in_ + rr * hn);
                float sold = At[(fb + j) * 72 + nl];
                out4[j] = (1.0f - zz) * ng + zz * sold;
            }
        }
        *reinterpret_cast<float4*>(s + (size_t)gn * 64 + fb) =
            make_float4(out4[0], out4[1], out4[2], out4[3]);
    }
}

// ---------------- t2 = s @ W2 [N,16] ------------------------------------------
__global__ void w2_kernel(const float* __restrict__ s, const float* __restrict__ W2,
                          float* __restrict__ t2, int n) {
    __shared__ float Wsm[64 * 16];
    for (int i = threadIdx.x; i < 64 * 16; i += blockDim.x) Wsm[i] = W2[i];
    __syncthreads();
    int node = blockIdx.x * 16 + threadIdx.x / 16;
    int c = threadIdx.x & 15;
    if (node >= n) return;
    const float4* srow = reinterpret_cast<const float4*>(s + (size_t)node * 64);
    float acc = 0.0f;
#pragma unroll
    for (int k4 = 0; k4 < 16; k4++) {
        float4 sv = __ldg(srow + k4);
        acc = fmaf(sv.x, Wsm[(k4 * 4 + 0) * 16 + c], acc);
        acc = fmaf(sv.y, Wsm[(k4 * 4 + 1) * 16 + c], acc);
        acc = fmaf(sv.z, Wsm[(k4 * 4 + 2) * 16 + c], acc);
        acc = fmaf(sv.w, Wsm[(k4 * 4 + 3) * 16 + c], acc);
    }
    t2[(size_t)node * 16 + c] = acc;
}

// ---------------- launch -------------------------------------------------------
extern "C" void kernel_launch(void* const* d_in, const int* in_sizes, int n_in,
                              void* d_out, int out_size) {
    const float* x   = (const float*)d_in[0];
    const int*   ei  = (const int*)  d_in[1];
    const float* ew  = (const float*)d_in[2];
    const float* W1  = (const float*)d_in[3];
    const float* b1  = (const float*)d_in[4];
    const float* Wg  = (const float*)d_in[5];
    const float* Wih = (const float*)d_in[6];
    const float* Whh = (const float*)d_in[7];
    const float* bih = (const float*)d_in[8];
    const float* bhh = (const float*)d_in[9];
    const float* W2  = (const float*)d_in[10];
    const float* b2  = (const float*)d_in[11];
    float* out = (float*)d_out;

    const int n = in_sizes[0] / 512;
    const int e = in_sizes[2];
    const int* row = ei;
    const int* col = ei + e;

    float *deg, *dinv, *t1, *s, *u, *t2, *wpl, *wnd, *wc, *whht;
    int *off, *cur, *srcs;
    cudaGetSymbolAddress((void**)&deg,  g_deg);
    cudaGetSymbolAddress((void**)&dinv, g_dinv);
    cudaGetSymbolAddress((void**)&t1,   g_t1);
    cudaGetSymbolAddress((void**)&s,    g_s);
    cudaGetSymbolAddress((void**)&u,    g_u);
    cudaGetSymbolAddress((void**)&t2,   g_t2);
    cudaGetSymbolAddress((void**)&off,  g_off);
    cudaGetSymbolAddress((void**)&cur,  g_cur);
    cudaGetSymbolAddress((void**)&srcs, g_srcs);
    cudaGetSymbolAddress((void**)&wpl,  g_wpl);
    cudaGetSymbolAddress((void**)&wnd,  g_wnd);
    cudaGetSymbolAddress((void**)&wc,   g_wc);
    cudaGetSymbolAddress((void**)&whht, g_whht);

    const int TB = 256;
    const int mblocks = (n + 127) / 128;
    const int gblocks = (n + 7) / 8;
    const int fblocks = (n + 63) / 64;
    const int FUSED_SMEM = (64 * 192 + 64 * 72) * sizeof(float);   // 67584 B

    static int smem_set = 0;
    if (!smem_set) {
        cudaFuncSetAttribute(ggc_fused_kernel,
                             cudaFuncAttributeMaxDynamicSharedMemorySize, FUSED_SMEM);
        smem_set = 1;
    }

    // ---- CSR build + shared gcn_norm ----
    init_kernel<<<(n + TB - 1) / TB, TB>>>(deg, cur, n);
    count_kernel<<<(e + TB - 1) / TB, TB>>>(col, ew, cur, deg, e);
    scan_kernel<<<1, 1024>>>(cur, off, cur, n);
    dinv_kernel<<<(n + TB - 1) / TB, TB>>>(deg, dinv, n);
    fill_kernel<<<(e + TB - 1) / TB, TB>>>(row, col, ew, dinv, cur, srcs, wpl, wnd, e);

    // combined GGC weights
    wc_kernel<<<(64 * 192 + TB - 1) / TB, TB>>>(Wg,           Wih, wc);
    wc_kernel<<<(64 * 192 + TB - 1) / TB, TB>>>(Wg + 64 * 64, Wih, wc + 64 * 192);
    whht_kernel<<<(64 * 192 + TB - 1) / TB, TB>>>(Whh, whht);

    // ---- GCN conv 1 ----
    gemm_kernel<128, 64, 16, 8, 4><<<dim3(mblocks, 1), 256>>>(x, W1, t1, n, 512, 64);
    gather64_kernel<1><<<gblocks, 256>>>(t1, t1, s, off, srcs, wnd, dinv, b1, n);

    // ---- GatedGraphConv (2 layers, fully fused per layer) ----
    for (int layer = 0; layer < 2; layer++) {
        gather64_kernel<0><<<gblocks, 256>>>(s, s, u, off, srcs, wpl, dinv, b1, n);
        ggc_fused_kernel<<<fblocks, 256, FUSED_SMEM>>>(
            u, s, wc + (size_t)layer * 64 * 192, whht, bih, bhh, n);
    }

    // ---- GCN conv 2 + log_softmax ----
    w2_kernel<<<(n + 15) / 16, 256>>>(s, W2, t2, n);
    gather16_lsm_kernel<<<gblocks, 256>>>(t2, out, off, srcs, wnd, dinv, b2, n);
}